// round 16
// baseline (speedup 1.0000x reference)
#include <cuda_runtime.h>
#include <cuda_bf16.h>
#include <math.h>
#include <stdint.h>

// Problem constants
constexpr int B  = 2;
constexpr int S  = 2048;
constexpr int D  = 1024;
constexpr int H  = 16;
constexpr int HD = 64;
constexpr int M  = B * S;       // 4096
constexpr int BH = B * H;       // 32

// ---------------------------------------------------------------------------
// Scratch (__device__ globals) — bf16 hi/lo split pairs.
// ---------------------------------------------------------------------------
__device__ __nv_bfloat16 g_Xh[3 * M * D],  g_Xl[3 * M * D];
__device__ __nv_bfloat16 g_Wh[4 * D * D],  g_Wl[4 * D * D];
__device__ __nv_bfloat16 g_Qh[BH * S * HD], g_Ql[BH * S * HD];   // [bh][s][hd]
__device__ __nv_bfloat16 g_Kh[BH * S * HD], g_Kl[BH * S * HD];   // [bh][s][hd]
__device__ __nv_bfloat16 g_Vth[BH * HD * S], g_Vtl[BH * HD * S]; // [bh][hd][s]

// ---------------------------------------------------------------------------
// PTX helpers (sm_80+ — valid on target sm_100)
// ---------------------------------------------------------------------------
__device__ __forceinline__ uint32_t smem_u32(const void* p) {
    uint32_t a;
    asm("{ .reg .u64 t; cvta.to.shared.u64 t, %1; cvt.u32.u64 %0, t; }"
        : "=r"(a) : "l"(p));
    return a;
}

__device__ __forceinline__ void ldmx4(uint32_t* r, uint32_t addr) {
    asm volatile("ldmatrix.sync.aligned.m8n8.x4.shared.b16 {%0,%1,%2,%3}, [%4];"
                 : "=r"(r[0]), "=r"(r[1]), "=r"(r[2]), "=r"(r[3]) : "r"(addr));
}

__device__ __forceinline__ void mma16816(float* d, const uint32_t* a,
                                         const uint32_t* b) {
    asm volatile(
        "mma.sync.aligned.m16n8k16.row.col.f32.bf16.bf16.f32 "
        "{%0,%1,%2,%3}, {%4,%5,%6,%7}, {%8,%9}, {%0,%1,%2,%3};"
        : "+f"(d[0]), "+f"(d[1]), "+f"(d[2]), "+f"(d[3])
        : "r"(a[0]), "r"(a[1]), "r"(a[2]), "r"(a[3]), "r"(b[0]), "r"(b[1]));
}

__device__ __forceinline__ void cp16(uint32_t saddr, const void* g) {
    asm volatile("cp.async.cg.shared.global [%0], [%1], 16;"
                 :: "r"(saddr), "l"(g));
}
#define CP_COMMIT() asm volatile("cp.async.commit_group;" ::: "memory")
#define CP_WAIT0()  asm volatile("cp.async.wait_group 0;" ::: "memory")

// fp32 pair -> (bf16x2 hi trunc, bf16x2 lo residual)
__device__ __forceinline__ void split2(float f0, float f1,
                                       uint32_t& hi, uint32_t& lo) {
    uint32_t u0 = __float_as_uint(f0), u1 = __float_as_uint(f1);
    hi = __byte_perm(u0, u1, 0x7632);
    float h0 = __uint_as_float(u0 & 0xFFFF0000u);
    float h1 = __uint_as_float(u1 & 0xFFFF0000u);
    __nv_bfloat162 l = __float22bfloat162_rn(make_float2(f0 - h0, f1 - h1));
    lo = *reinterpret_cast<uint32_t*>(&l);
}
__device__ __forceinline__ void split1(float f, __nv_bfloat16& hi,
                                       __nv_bfloat16& lo) {
    uint32_t u = __float_as_uint(f);
    __nv_bfloat16_raw hr; hr.x = (unsigned short)(u >> 16);
    hi = hr;
    float hf = __uint_as_float(u & 0xFFFF0000u);
    lo = __float2bfloat16_rn(f - hf);
}

// ---------------------------------------------------------------------------
// Fused fp32 -> bf16 hi/lo split for all 7 inputs in ONE launch.
// ---------------------------------------------------------------------------
__global__ __launch_bounds__(256)
void cvt_all(const float4* __restrict__ q,  const float4* __restrict__ k,
             const float4* __restrict__ v,  const float4* __restrict__ wq,
             const float4* __restrict__ wk, const float4* __restrict__ wv,
             const float4* __restrict__ wo)
{
    const int which = blockIdx.y;
    const int i = blockIdx.x * blockDim.x + threadIdx.x;
    const float4* src;
    uint2 *hi, *lo;
    int nvec;
    if (which < 3) {
        src = (which == 0) ? q : (which == 1) ? k : v;
        hi = (uint2*)g_Xh + (size_t)which * (M * D / 4);
        lo = (uint2*)g_Xl + (size_t)which * (M * D / 4);
        nvec = M * D / 4;
    } else {
        const int ws = which - 3;
        src = (ws == 0) ? wq : (ws == 1) ? wk : (ws == 2) ? wv : wo;
        hi = (uint2*)g_Wh + (size_t)ws * (D * D / 4);
        lo = (uint2*)g_Wl + (size_t)ws * (D * D / 4);
        nvec = D * D / 4;
    }
    if (i >= nvec) return;
    float4 x = src[i];
    uint2 h, l;
    split2(x.x, x.y, h.x, l.x);
    split2(x.z, x.w, h.y, l.y);
    hi[i] = h;
    lo[i] = l;
}

// ---------------------------------------------------------------------------
// mma.sync GEMM (UNCHANGED, tensor=51.9%): 128x128 tile, 2 CTAs/SM.
// ---------------------------------------------------------------------------
constexpr int GROWB = 80;
constexpr int GTILE = 128 * GROWB;         // 10240 B
constexpr int GBUF  = 4 * GTILE;           // 40960 B
constexpr int GEMM_SMEM = 2 * GBUF;        // 81920 B

__global__ __launch_bounds__(256, 2)
void gemm_mma(float* __restrict__ Out, int omode)
{
    extern __shared__ __align__(128) char smem[];
    const uint32_t sb = smem_u32(smem);
    const int tid  = threadIdx.x;
    const int lane = tid & 31;
    const int wid  = tid >> 5;
    const int wm   = wid >> 2;
    const int wn   = wid & 3;
    const int col0 = blockIdx.x * 128;
    const int row0 = blockIdx.y * 128;
    const int z    = blockIdx.z;

    int xs, ws, mode;
    float scale;
    if (omode == 0) { xs = 0; ws = 3; scale = 1.0f;  mode = 0; }
    else            { xs = z; ws = z; scale = (z == 0) ? 0.125f : 1.0f; mode = 1 + z; }

    const __nv_bfloat16* srcs[4] = {
        g_Xh + (size_t)xs * M * D + (size_t)row0 * D,
        g_Xl + (size_t)xs * M * D + (size_t)row0 * D,
        g_Wh + (size_t)ws * D * D + (size_t)col0 * D,
        g_Wl + (size_t)ws * D * D + (size_t)col0 * D };

    auto load_chunk = [&](int kt, int buf) {
        const uint32_t bs = sb + buf * GBUF;
        const int kbytes = kt * 64;
        #pragma unroll
        for (int t = 0; t < 4; t++) {
            const char* g = (const char*)srcs[t] + kbytes;
            const uint32_t sd = bs + t * GTILE;
            #pragma unroll
            for (int p = 0; p < 2; p++) {
                int u = tid + p * 256;
                int r = u >> 2, c16 = (u & 3) * 16;
                cp16(sd + r * GROWB + c16, g + (size_t)r * 2048 + c16);
            }
        }
    };

    float c[4][4][4] = {};

    load_chunk(0, 0);
    CP_COMMIT();
    CP_WAIT0();
    __syncthreads();

    for (int kt = 0; kt < 32; kt++) {
        const int buf = kt & 1;
        if (kt < 31) { load_chunk(kt + 1, buf ^ 1); CP_COMMIT(); }

        const uint32_t base = sb + buf * GBUF;
        #pragma unroll
        for (int ks = 0; ks < 2; ks++) {
            const int k0 = ks * 16;
            uint32_t ah[4][4], al[4][4];
            {
                const uint32_t rofs = (uint32_t)(wm * 64 + (lane & 15)) * GROWB
                                    + (uint32_t)(k0 + (lane >> 4) * 8) * 2;
                #pragma unroll
                for (int i = 0; i < 4; i++) {
                    ldmx4(ah[i], base + 0 * GTILE + rofs + i * 16 * GROWB);
                    ldmx4(al[i], base + 1 * GTILE + rofs + i * 16 * GROWB);
                }
            }
            uint32_t bh[4][2], bl[4][2];
            {
                const uint32_t rpart = (uint32_t)(wn * 32 + (lane >> 4) * 8
                                                  + (lane & 7)) * GROWB
                                     + (uint32_t)(k0 + ((lane >> 3) & 1) * 8) * 2;
                #pragma unroll
                for (int pr = 0; pr < 2; pr++) {
                    uint32_t r4[4];
                    ldmx4(r4, base + 2 * GTILE + rpart + pr * 16 * GROWB);
                    bh[pr * 2 + 0][0] = r4[0]; bh[pr * 2 + 0][1] = r4[1];
                    bh[pr * 2 + 1][0] = r4[2]; bh[pr * 2 + 1][1] = r4[3];
                    ldmx4(r4, base + 3 * GTILE + rpart + pr * 16 * GROWB);
                    bl[pr * 2 + 0][0] = r4[0]; bl[pr * 2 + 0][1] = r4[1];
                    bl[pr * 2 + 1][0] = r4[2]; bl[pr * 2 + 1][1] = r4[3];
                }
            }
            #pragma unroll
            for (int i = 0; i < 4; i++)
                #pragma unroll
                for (int j = 0; j < 4; j++) {
                    mma16816(c[i][j], ah[i], bh[j]);
                    mma16816(c[i][j], ah[i], bl[j]);
                    mma16816(c[i][j], al[i], bh[j]);
                }
        }
        if (kt < 31) CP_WAIT0();
        __syncthreads();
    }

    const int g = lane >> 2, t2 = (lane & 3) * 2;
    #pragma unroll
    for (int i = 0; i < 4; i++) {
        #pragma unroll
        for (int half = 0; half < 2; half++) {
            const int gr = row0 + wm * 64 + i * 16 + g + half * 8;
            #pragma unroll
            for (int j = 0; j < 4; j++) {
                const int gc = col0 + wn * 32 + j * 8 + t2;
                float f0 = c[i][j][half * 2 + 0] * scale;
                float f1 = c[i][j][half * 2 + 1] * scale;
                if (mode == 0) {
                    *(float2*)&Out[(size_t)gr * D + gc] = make_float2(f0, f1);
                } else {
                    const int b = gr >> 11, s_ = gr & (S - 1);
                    const int h = gc >> 6, hd = gc & 63;
                    if (mode == 3) {   // transposed V
                        const size_t rb = (size_t)(b * H + h) * HD;
                        __nv_bfloat16 hi, lo;
                        split1(f0, hi, lo);
                        g_Vth[(rb + hd) * S + s_] = hi;
                        g_Vtl[(rb + hd) * S + s_] = lo;
                        split1(f1, hi, lo);
                        g_Vth[(rb + hd + 1) * S + s_] = hi;
                        g_Vtl[(rb + hd + 1) * S + s_] = lo;
                    } else {
                        __nv_bfloat16* dh = (mode == 1) ? g_Qh : g_Kh;
                        __nv_bfloat16* dl = (mode == 1) ? g_Ql : g_Kl;
                        const size_t idx = (((size_t)(b * H + h) * S) + s_) * HD + hd;
                        uint32_t hi, lo;
                        split2(f0, f1, hi, lo);
                        ((uint32_t*)dh)[idx >> 1] = hi;
                        ((uint32_t*)dl)[idx >> 1] = lo;
                    }
                }
            }
        }
    }
}

// ---------------------------------------------------------------------------
// Tensor-core flash attention: k-tile 64 -> smem 110592 B -> 2 CTAs/SM.
// CTA = 128 q-rows x (b,h); 8 warps each own m16 x n64 of the score tile.
// ---------------------------------------------------------------------------
constexpr int TROWB   = 144;                       // 64 halves + 8 pad
constexpr int VROWB   = 144;                       // 64 halves + 8 pad
constexpr int QH_OFF  = 0;
constexpr int QL_OFF  = 18432;                     // 128*144
constexpr int KBUF_OFF = 36864;  // 2 bufs stride 18432 (Kh 9216 + Kl 9216)
constexpr int VBUF_OFF = 73728;  // 2 bufs stride 18432 (Vh 9216 + Vl 9216)
constexpr int ATT_SMEM = 110592;

__global__ __launch_bounds__(256, 2)
void attn_mma()
{
    extern __shared__ __align__(128) char smem[];
    const uint32_t sb = smem_u32(smem);
    const int tid  = threadIdx.x;
    const int lane = tid & 31;
    const int wid  = tid >> 5;
    const int qt   = 15 - (int)blockIdx.x;     // heavy q-tiles first
    const int bhi  = blockIdx.y;
    const int q0   = qt * 128;
    const int nkt  = 2 * qt + 2;               // number of 64-wide k-tiles

    const char* Qhp = (const char*)(g_Qh + (size_t)bhi * S * HD) + (size_t)q0 * 128;
    const char* Qlp = (const char*)(g_Ql + (size_t)bhi * S * HD) + (size_t)q0 * 128;
    const char* Khp = (const char*)(g_Kh + (size_t)bhi * S * HD);
    const char* Klp = (const char*)(g_Kl + (size_t)bhi * S * HD);
    const char* Vhp = (const char*)(g_Vth + (size_t)bhi * HD * S);
    const char* Vlp = (const char*)(g_Vtl + (size_t)bhi * HD * S);

    // Q tiles (once): 128 rows x 128B, hi+lo — cp.async
    #pragma unroll
    for (int p = 0; p < 4; p++) {
        int u = tid + p * 256;
        int r = u >> 3, c16 = (u & 7) * 16;
        cp16(sb + QH_OFF + r * TROWB + c16, Qhp + (size_t)r * 128 + c16);
        cp16(sb + QL_OFF + r * TROWB + c16, Qlp + (size_t)r * 128 + c16);
    }

    // K/V tile loader: 64 rows x 128B each of Kh,Kl,Vh,Vl (8 cp16/thread)
    auto loadKV = [&](int kt, int buf) {
        const uint32_t kb = sb + KBUF_OFF + buf * 18432;
        const uint32_t vb = sb + VBUF_OFF + buf * 18432;
        const size_t kbyte = (size_t)kt * 64 * 128;    // K row offset (bytes)
        const size_t vbyte = (size_t)kt * 64 * 2;      // V col offset (bytes)
        #pragma unroll
        for (int p = 0; p < 2; p++) {
            int u = tid + p * 256;
            int r = u >> 3, c16 = (u & 7) * 16;
            cp16(kb + r * TROWB + c16,        Khp + kbyte + (size_t)r * 128 + c16);
            cp16(kb + 9216 + r * TROWB + c16, Klp + kbyte + (size_t)r * 128 + c16);
            cp16(vb + r * VROWB + c16,        Vhp + (size_t)r * (S * 2) + vbyte + c16);
            cp16(vb + 9216 + r * VROWB + c16, Vlp + (size_t)r * (S * 2) + vbyte + c16);
        }
    };

    loadKV(0, 0);
    CP_COMMIT();
    CP_WAIT0();
    __syncthreads();

    float o[8][4] = {};
    float mrow[2] = {-1e30f, -1e30f}, lrow[2] = {0.f, 0.f};

    const uint32_t a_rofs = (uint32_t)(wid * 16 + (lane & 15)) * TROWB
                          + (uint32_t)((lane >> 4) * 8) * 2;
    const uint32_t b_rofs = (uint32_t)((lane >> 4) * 8 + (lane & 7)) * TROWB
                          + (uint32_t)(((lane >> 3) & 1) * 8) * 2;
    const uint32_t v_rofs = (uint32_t)((lane >> 4) * 8 + (lane & 7)) * VROWB
                          + (uint32_t)(((lane >> 3) & 1) * 8) * 2;

    for (int kt = 0; kt < nkt; kt++) {
        const int buf = kt & 1;
        if (kt + 1 < nkt) { loadKV(kt + 1, buf ^ 1); CP_COMMIT(); }

        // ----- S = Q.K^T (fp32 accum, 3-way split); n = 64 keys -----
        float sf[8][4] = {};
        const uint32_t kb = sb + KBUF_OFF + buf * 18432;
        #pragma unroll
        for (int ks = 0; ks < 4; ks++) {
            uint32_t ah[4], al[4];
            ldmx4(ah, sb + QH_OFF + a_rofs + ks * 32);
            ldmx4(al, sb + QL_OFF + a_rofs + ks * 32);
            #pragma unroll
            for (int jj = 0; jj < 4; jj++) {
                uint32_t r4[4], l4[4];
                ldmx4(r4, kb + jj * 16 * TROWB + b_rofs + ks * 32);
                ldmx4(l4, kb + 9216 + jj * 16 * TROWB + b_rofs + ks * 32);
                uint32_t b0h[2] = {r4[0], r4[1]}, b1h[2] = {r4[2], r4[3]};
                uint32_t b0l[2] = {l4[0], l4[1]}, b1l[2] = {l4[2], l4[3]};
                mma16816(sf[2 * jj],     ah, b0h);
                mma16816(sf[2 * jj],     ah, b0l);
                mma16816(sf[2 * jj],     al, b0h);
                mma16816(sf[2 * jj + 1], ah, b1h);
                mma16816(sf[2 * jj + 1], ah, b1l);
                mma16816(sf[2 * jj + 1], al, b1h);
            }
        }

        // ----- causal mask on the last two tiles -----
        if (kt >= 2 * qt) {
            const int rel = (kt - 2 * qt) * 64;   // 0 or 64
            const int rb = wid * 16 + (lane >> 2);
            const int cb = (lane & 3) * 2;
            #pragma unroll
            for (int j = 0; j < 8; j++)
                #pragma unroll
                for (int e = 0; e < 4; e++) {
                    int row = rb + (e >> 1) * 8;
                    int col = j * 8 + cb + (e & 1) + rel;
                    if (col > row) sf[j][e] = -1e30f;
                }
        }

        // ----- online softmax (rows live in 4-lane quads) -----
        #pragma unroll
        for (int h2 = 0; h2 < 2; h2++) {
            float mx = -1e30f;
            #pragma unroll
            for (int j = 0; j < 8; j++)
                mx = fmaxf(mx, fmaxf(sf[j][h2 * 2], sf[j][h2 * 2 + 1]));
            mx = fmaxf(mx, __shfl_xor_sync(0xffffffffu, mx, 1));
            mx = fmaxf(mx, __shfl_xor_sync(0xffffffffu, mx, 2));
            const float mn   = fmaxf(mrow[h2], mx);
            const float corr = __expf(mrow[h2] - mn);
            float rs = 0.f;
            #pragma unroll
            for (int j = 0; j < 8; j++) {
                sf[j][h2 * 2]     = __expf(sf[j][h2 * 2]     - mn);
                sf[j][h2 * 2 + 1] = __expf(sf[j][h2 * 2 + 1] - mn);
                rs += sf[j][h2 * 2] + sf[j][h2 * 2 + 1];
            }
            rs += __shfl_xor_sync(0xffffffffu, rs, 1);
            rs += __shfl_xor_sync(0xffffffffu, rs, 2);
            lrow[h2] = lrow[h2] * corr + rs;
            mrow[h2] = mn;
            #pragma unroll
            for (int j = 0; j < 8; j++) {
                o[j][h2 * 2]     *= corr;
                o[j][h2 * 2 + 1] *= corr;
            }
        }

        // ----- O += P.V (P split from S accumulators; V transposed) -----
        const uint32_t vb = sb + VBUF_OFF + buf * 18432;
        #pragma unroll
        for (int ks2 = 0; ks2 < 4; ks2++) {
            uint32_t pah[4], pal[4];
            #pragma unroll
            for (int t = 0; t < 2; t++)
                #pragma unroll
                for (int h2 = 0; h2 < 2; h2++)
                    split2(sf[2 * ks2 + t][h2 * 2], sf[2 * ks2 + t][h2 * 2 + 1],
                           pah[t * 2 + h2], pal[t * 2 + h2]);
            #pragma unroll
            for (int jj = 0; jj < 4; jj++) {
                uint32_t r4[4], l4[4];
                ldmx4(r4, vb + jj * 16 * VROWB + v_rofs + ks2 * 32);
                ldmx4(l4, vb + 9216 + jj * 16 * VROWB + v_rofs + ks2 * 32);
                uint32_t b0h[2] = {r4[0], r4[1]}, b1h[2] = {r4[2], r4[3]};
                uint32_t b0l[2] = {l4[0], l4[1]}, b1l[2] = {l4[2], l4[3]};
                mma16816(o[2 * jj],     pah, b0h);
                mma16816(o[2 * jj],     pah, b0l);
                mma16816(o[2 * jj],     pal, b0h);
                mma16816(o[2 * jj + 1], pah, b1h);
                mma16816(o[2 * jj + 1], pah, b1l);
                mma16816(o[2 * jj + 1], pal, b1h);
            }
        }
        if (kt + 1 < nkt) CP_WAIT0();
        __syncthreads();
    }

    // ----- epilogue: normalize + split-write into X slot 0 -----
    const int b = bhi >> 4, h = bhi & 15;
    const int r = lane >> 2, c2 = (lane & 3) * 2;
    #pragma unroll
    for (int h2 = 0; h2 < 2; h2++) {
        const int row = b * S + q0 + wid * 16 + r + h2 * 8;
        const float inv = 1.f / lrow[h2];
        #pragma unroll
        for (int j = 0; j < 8; j++) {
            const int col = h * 64 + j * 8 + c2;
            uint32_t hi, lo;
            split2(o[j][h2 * 2] * inv, o[j][h2 * 2 + 1] * inv, hi, lo);
            const size_t idx = (size_t)row * D + col;
            ((uint32_t*)g_Xh)[idx >> 1] = hi;
            ((uint32_t*)g_Xl)[idx >> 1] = lo;
        }
    }
}

// ---------------------------------------------------------------------------
extern "C" void kernel_launch(void* const* d_in, const int* in_sizes, int n_in,
                              void* d_out, int out_size)
{
    const float* q  = (const float*)d_in[0];
    const float* k  = (const float*)d_in[1];
    const float* v  = (const float*)d_in[2];
    const float* wq = (const float*)d_in[3];
    const float* wk = (const float*)d_in[4];
    const float* wv = (const float*)d_in[5];
    const float* wo = (const float*)d_in[6];
    float* out = (float*)d_out;

    cudaFuncSetAttribute(gemm_mma, cudaFuncAttributeMaxDynamicSharedMemorySize,
                         GEMM_SMEM);
    cudaFuncSetAttribute(attn_mma, cudaFuncAttributeMaxDynamicSharedMemorySize,
                         ATT_SMEM);

    // one fused split pass for all 7 inputs
    dim3 cb(256);
    dim3 cvg((M * D / 4 + 255) / 256, 7);        // (4096, 7)
    cvt_all<<<cvg, cb>>>((const float4*)q,  (const float4*)k,
                         (const float4*)v,  (const float4*)wq,
                         (const float4*)wk, (const float4*)wv,
                         (const float4*)wo);

    // fused Q/K/V projections
    gemm_mma<<<dim3(D / 128, M / 128, 3), cb, GEMM_SMEM>>>(nullptr, 1);

    // attention -> writes X slot 0
    attn_mma<<<dim3(16, BH), cb, ATT_SMEM>>>();

    // output projection
    gemm_mma<<<dim3(D / 128, M / 128, 1), cb, GEMM_SMEM>>>(out, 0);
}